// round 7
// baseline (speedup 1.0000x reference)
#include <cuda_runtime.h>

// Voronoi nearest-site, fused-entry LUT. Reference-exact fp32 compare:
//   a  = rn(rn(x0^2) + rn(x1^2))
//   e  = fmaf(x1, sy, rn(x0*sx))
//   d2 = rn(rn(a - 2*e) + cs),  cs = rn(rn(sx^2) + rn(sy^2))
//   argmin: ascending candidate order, strict <  (lowest-index tie-break)
//
// R6 -> R7: grid entry = float4. Single-candidate cell: (r,g,b, w=0) ->
// fast path is ONE LDS.128, no index decode, no second gather. Multi cell:
// 16 id bytes across w,x,y,z (ascending, 0xFF pad; w=0xFFFFFFFE => 5x5
// fallback, effectively never). GR=48 -> 40.1KB static smem, 5 CTAs/SM,
// 740 CTAs = one wave. 4 adjacent points/thread: LDG.128 in, STG.128 out.

#define GR 48
#define NS 100
#define NCELL (GR * GR)

__device__ float4 g_entry[NCELL];
__device__ float4 g_cand[NS];   // sx, sy, cs, 0
__device__ float4 g_rgb[NS];    // r, g, b, 0

__global__ void build_lut(const float* __restrict__ p) {
    __shared__ float sp[2 * NS];
    for (int i = threadIdx.x; i < 2 * NS; i += blockDim.x) {
        int s = i >> 1;
        sp[i] = p[1 + 5 * s + (i & 1)];
    }
    __syncthreads();

    int cell = blockIdx.x * blockDim.x + threadIdx.x;
    if (cell >= NCELL) return;

    if (cell < NS) {
        float sx = sp[2 * cell], sy = sp[2 * cell + 1];
        float cs = __fadd_rn(__fmul_rn(sx, sx), __fmul_rn(sy, sy));
        g_cand[cell] = make_float4(sx, sy, cs, 0.0f);
        g_rgb[cell]  = make_float4(p[3 + 5 * cell], p[4 + 5 * cell], p[5 + 5 * cell], 0.0f);
    }

    int gy = cell / GR;
    int gx = cell - gy * GR;

    // 4 sub-quadrant centers; any p in cell is within r4 = sqrt(2)/(4*GR) of
    // one. Include s iff exists q: d(q,s) <= m(q) + 2*r4 + slack.
    float qxv[2] = { (gx + 0.25f) * (1.0f / GR), (gx + 0.75f) * (1.0f / GR) };
    float qyv[2] = { (gy + 0.25f) * (1.0f / GR), (gy + 0.75f) * (1.0f / GR) };

    // 5x5 coarse window covering all subcenters (nearest site + full band
    // provably inside: max relevant distance 0.1414+0.015 < 0.2).
    int i0 = max(0, (int)(qxv[0] * 10.0f) - 2);
    int i1 = min(9, (int)(qxv[1] * 10.0f) + 2);
    int j0 = max(0, (int)(qyv[0] * 10.0f) - 2);
    int j1 = min(9, (int)(qyv[1] * 10.0f) + 2);

    float m[4] = {3.4e38f, 3.4e38f, 3.4e38f, 3.4e38f};
    for (int ii = i0; ii <= i1; ii++)
        for (int jj = j0; jj <= j1; jj++) {
            int s = ii * 10 + jj;
            float sx = sp[2 * s], sy = sp[2 * s + 1];
            #pragma unroll
            for (int k = 0; k < 4; k++) {
                float dx = qxv[k & 1] - sx, dy = qyv[k >> 1] - sy;
                m[k] = fminf(m[k], fmaf(dx, dx, dy * dy));
            }
        }

    float thr[4];
    const float band = 0.0147314f + 1e-4f;   // sqrt(2)/(2*48) + slack
    #pragma unroll
    for (int k = 0; k < 4; k++) {
        float t = sqrtf(m[k]) + band;
        thr[k] = t * t;
    }

    unsigned int words[4] = {0xFFFFFFFFu, 0xFFFFFFFFu, 0xFFFFFFFFu, 0xFFFFFFFFu};
    int cnt = 0;
    int first = 0;
    for (int ii = i0; ii <= i1; ii++)
        for (int jj = j0; jj <= j1; jj++) {       // ascending site ids
            int s = ii * 10 + jj;
            float sx = sp[2 * s], sy = sp[2 * s + 1];
            bool inc = false;
            #pragma unroll
            for (int k = 0; k < 4; k++) {
                float dx = qxv[k & 1] - sx, dy = qyv[k >> 1] - sy;
                inc |= (fmaf(dx, dx, dy * dy) <= thr[k]);
            }
            if (inc) {
                if (cnt == 0) first = s;
                if (cnt < 16) {
                    int wi = cnt >> 2, b = (cnt & 3) * 8;
                    words[wi] = (words[wi] & ~(0xFFu << b)) | ((unsigned int)s << b);
                }
                cnt++;
            }
        }

    float4 entry;
    if (cnt == 1) {
        float4 c = g_rgb[first];   // just built above if first<NS... read global (coherent: same kernel? no) 
        // NOTE: g_rgb may be written by another thread in this grid; read from p directly instead.
        entry = make_float4(p[3 + 5 * first], p[4 + 5 * first], p[5 + 5 * first], 0.0f);
        (void)c;
    } else if (cnt <= 16) {
        // byte layout: e.w = ids 0..3, e.x = 4..7, e.y = 8..11, e.z = 12..15
        entry = make_float4(__uint_as_float(words[1]), __uint_as_float(words[2]),
                            __uint_as_float(words[3]), __uint_as_float(words[0]));
    } else {
        entry = make_float4(0.0f, 0.0f, 0.0f, __uint_as_float(0xFFFFFFFEu));
    }
    g_entry[cell] = entry;
}

struct SmemTables {
    float4 grid[NCELL];   // 36864 B
    float4 cand[NS];      //  1600 B
    float4 rgb[NS];       //  1600 B
};

// Evaluate <=4 candidate bytes of one word; returns true when a pad byte ends the list.
__device__ __forceinline__ bool eval_word(
    unsigned int v, float px, float py, float a,
    const float4* __restrict__ scand, float& bd, int& bi)
{
    #pragma unroll
    for (int b = 0; b < 4; b++) {
        unsigned int c = (v >> (8 * b)) & 0xFFu;
        if (c >= 100u) return true;
        float4 s = scand[c];
        float ee = __fmaf_rn(py, s.y, __fmul_rn(px, s.x));
        float d2 = __fadd_rn(__fsub_rn(a, __fmul_rn(2.0f, ee)), s.z);
        if (d2 < bd) { bd = d2; bi = (int)c; }
    }
    return false;
}

__device__ __forceinline__ float4 lookup_one(
    float px, float py,
    const float4* __restrict__ sgrid,
    const float4* __restrict__ scand,
    const float4* __restrict__ srgb)
{
    int cx = (int)(px * (float)GR);   // x in [0,1): no clamp needed
    int cy = (int)(py * (float)GR);
    float4 e = sgrid[cy * GR + cx];
    unsigned int w0 = __float_as_uint(e.w);

    if (w0 != 0u) {
        float a = __fadd_rn(__fmul_rn(px, px), __fmul_rn(py, py));
        float bd = 3.4e38f;
        int bi = 0;
        if (w0 == 0xFFFFFFFEu) {
            // 5x5 coarse scan fallback (ascending ids) — effectively never.
            int ci = (int)(px * 10.0f);
            int cj = (int)(py * 10.0f);
            int i1 = min(9, ci + 2), j0 = max(0, cj - 2), j1 = min(9, cj + 2);
            for (int ii = max(0, ci - 2); ii <= i1; ii++)
                for (int jj = j0; jj <= j1; jj++) {
                    int s = ii * 10 + jj;
                    float4 c = scand[s];
                    float ee = __fmaf_rn(py, c.y, __fmul_rn(px, c.x));
                    float d2 = __fadd_rn(__fsub_rn(a, __fmul_rn(2.0f, ee)), c.z);
                    if (d2 < bd) { bd = d2; bi = s; }
                }
        } else {
            if (!eval_word(w0, px, py, a, scand, bd, bi))
                if (!eval_word(__float_as_uint(e.x), px, py, a, scand, bd, bi))
                    if (!eval_word(__float_as_uint(e.y), px, py, a, scand, bd, bi))
                        eval_word(__float_as_uint(e.z), px, py, a, scand, bd, bi);
        }
        e = srgb[bi];
    }
    return e;
}

__global__ void __launch_bounds__(256, 5) voronoi_main(
    const float4* __restrict__ x4, float* __restrict__ out, int n)
{
    __shared__ SmemTables st;

    {
        const uint4* gg = (const uint4*)g_entry;
        uint4* sg = (uint4*)st.grid;
        for (int i = threadIdx.x; i < NCELL; i += 256) sg[i] = gg[i];
        if (threadIdx.x < NS) {
            st.cand[threadIdx.x] = g_cand[threadIdx.x];
            st.rgb[threadIdx.x]  = g_rgb[threadIdx.x];
        }
    }
    __syncthreads();

    float4* out4 = (float4*)out;
    int tid = blockIdx.x * blockDim.x + threadIdx.x;
    int stride = gridDim.x * blockDim.x;
    int ngroups = n >> 2;

    for (int g = tid; g < ngroups; g += stride) {
        float4 xa = x4[2 * g + 0];
        float4 xb = x4[2 * g + 1];

        float4 c0 = lookup_one(xa.x, xa.y, st.grid, st.cand, st.rgb);
        float4 c1 = lookup_one(xa.z, xa.w, st.grid, st.cand, st.rgb);
        float4 c2 = lookup_one(xb.x, xb.y, st.grid, st.cand, st.rgb);
        float4 c3 = lookup_one(xb.z, xb.w, st.grid, st.cand, st.rgb);

        out4[3 * g + 0] = make_float4(c0.x, c0.y, c0.z, c1.x);
        out4[3 * g + 1] = make_float4(c1.y, c1.z, c2.x, c2.y);
        out4[3 * g + 2] = make_float4(c2.z, c3.x, c3.y, c3.z);
    }

    // Remainder (n % 4) — scalar path.
    int rem_start = ngroups << 2;
    for (int i = rem_start + tid; i < n; i += stride) {
        const float2* x2 = (const float2*)x4;
        float2 pt = x2[i];
        float4 c = lookup_one(pt.x, pt.y, st.grid, st.cand, st.rgb);
        out[3 * i + 0] = c.x;
        out[3 * i + 1] = c.y;
        out[3 * i + 2] = c.z;
    }
}

extern "C" void kernel_launch(void* const* d_in, const int* in_sizes, int n_in,
                              void* d_out, int out_size) {
    const float4* x = (const float4*)d_in[0];
    const float*  p = (const float*)d_in[1];
    float* out = (float*)d_out;
    int n = in_sizes[0] / 2;

    build_lut<<<(NCELL + 63) / 64, 64>>>(p);
    voronoi_main<<<740, 256>>>(x, out, n);
}

// round 8
// speedup vs baseline: 1.0608x; 1.0608x over previous
#include <cuda_runtime.h>

// Voronoi nearest-site, uniform 2-candidate LUT. Reference-exact fp32:
//   a  = rn(rn(x0^2) + rn(x1^2))
//   e  = fmaf(x1, sy, rn(x0*sx))
//   d2 = rn(rn(a - 2*e) + cs),  cs = rn(rn(sx^2) + rn(sy^2))
//   argmin: ascending candidate order, strict <  (lowest-index tie-break)
//
// R7 -> R8 (structural): ~half of all fine cells straddle a Voronoi edge, so
// the single-cand "fast path" was never the common case and every warp paid
// both sides of the branch. New layout: u32 entry = id0|id1<<8|hi<<16.
//   - ALL lanes uniformly evaluate id0 and id1 (1-cand cells store id1=id0;
//     duplicates can't win under strict <).
//   - hi==0xFFFF: done. hi==0xFEFE: 5x5 coarse fallback (degenerate, ~0).
//     else: 2 more evals (ids 3..4, near Voronoi vertices, ~3-5% of cells).
// GR=88 -> 31KB smem, 6 CTAs/SM, 888 CTAs one wave; 2 stride-points/thread.

#define GR 88
#define NS 100
#define NCELL (GR * GR)

__device__ unsigned int g_grid[NCELL];
__device__ float4 g_cand[NS];   // sx, sy, cs, 0
__device__ float4 g_rgb[NS];    // r, g, b, 0

__global__ void build_lut(const float* __restrict__ p) {
    __shared__ float sp[2 * NS];
    for (int i = threadIdx.x; i < 2 * NS; i += blockDim.x) {
        int s = i >> 1;
        sp[i] = p[1 + 5 * s + (i & 1)];
    }
    __syncthreads();

    int cell = blockIdx.x * blockDim.x + threadIdx.x;
    if (cell >= NCELL) return;

    if (cell < NS) {
        float sx = sp[2 * cell], sy = sp[2 * cell + 1];
        float cs = __fadd_rn(__fmul_rn(sx, sx), __fmul_rn(sy, sy));
        g_cand[cell] = make_float4(sx, sy, cs, 0.0f);
        g_rgb[cell]  = make_float4(p[3 + 5 * cell], p[4 + 5 * cell], p[5 + 5 * cell], 0.0f);
    }

    int gy = cell / GR;
    int gx = cell - gy * GR;

    // 4 sub-quadrant centers; any p in cell is within sqrt(2)/(4*GR) of one.
    // Include s iff exists q: d(q,s) <= m(q) + sqrt(2)/(2*GR) + slack.
    float qxv[2] = { (gx + 0.25f) * (1.0f / GR), (gx + 0.75f) * (1.0f / GR) };
    float qyv[2] = { (gy + 0.25f) * (1.0f / GR), (gy + 0.75f) * (1.0f / GR) };

    // 5x5 coarse window around the cell covers the nearest site (<=0.1415)
    // plus the whole band (<0.2 guaranteed reach).
    int i0 = max(0, (int)(qxv[0] * 10.0f) - 2);
    int i1 = min(9, (int)(qxv[1] * 10.0f) + 2);
    int j0 = max(0, (int)(qyv[0] * 10.0f) - 2);
    int j1 = min(9, (int)(qyv[1] * 10.0f) + 2);

    float m[4] = {3.4e38f, 3.4e38f, 3.4e38f, 3.4e38f};
    for (int ii = i0; ii <= i1; ii++)
        for (int jj = j0; jj <= j1; jj++) {
            int s = ii * 10 + jj;
            float sx = sp[2 * s], sy = sp[2 * s + 1];
            #pragma unroll
            for (int k = 0; k < 4; k++) {
                float dx = qxv[k & 1] - sx, dy = qyv[k >> 1] - sy;
                m[k] = fminf(m[k], fmaf(dx, dx, dy * dy));
            }
        }

    float thr[4];
    const float band = 0.0080349f + 1e-4f;   // sqrt(2)/(2*88) + slack
    #pragma unroll
    for (int k = 0; k < 4; k++) {
        float t = sqrtf(m[k]) + band;
        thr[k] = t * t;
    }

    unsigned int ids[4] = {0, 0, 0, 0};
    int cnt = 0;
    for (int ii = i0; ii <= i1; ii++)
        for (int jj = j0; jj <= j1; jj++) {   // ascending site ids
            int s = ii * 10 + jj;
            float sx = sp[2 * s], sy = sp[2 * s + 1];
            bool inc = false;
            #pragma unroll
            for (int k = 0; k < 4; k++) {
                float dx = qxv[k & 1] - sx, dy = qyv[k >> 1] - sy;
                inc |= (fmaf(dx, dx, dy * dy) <= thr[k]);
            }
            if (inc) {
                if (cnt < 4) ids[cnt] = (unsigned int)s;
                cnt++;
            }
        }

    unsigned int entry;
    if (cnt <= 1) {
        entry = ids[0] | (ids[0] << 8) | 0xFFFF0000u;          // dup: can't win
    } else if (cnt == 2) {
        entry = ids[0] | (ids[1] << 8) | 0xFFFF0000u;
    } else if (cnt == 3) {
        entry = ids[0] | (ids[1] << 8) | (ids[2] << 16) | (ids[2] << 24);
    } else if (cnt == 4) {
        entry = ids[0] | (ids[1] << 8) | (ids[2] << 16) | (ids[3] << 24);
    } else {
        entry = ids[0] | (ids[1] << 8) | 0xFEFE0000u;          // 5x5 fallback
    }
    g_grid[cell] = entry;
}

struct SmemTables {
    unsigned int grid[NCELL];   // 30976 B
    float4 cand[NS];            //  1600 B
    float4 rgb[NS];             //  1600 B
};

__device__ __forceinline__ void eval_cand(
    unsigned int c, float px, float py, float a,
    const float4* __restrict__ scand, float& bd, int& bi)
{
    float4 s = scand[c];
    float ee = __fmaf_rn(py, s.y, __fmul_rn(px, s.x));
    float d2 = __fadd_rn(__fsub_rn(a, __fmul_rn(2.0f, ee)), s.z);
    if (d2 < bd) { bd = d2; bi = (int)c; }
}

__device__ __forceinline__ float4 lookup_one(
    float px, float py,
    const unsigned int* __restrict__ sgrid,
    const float4* __restrict__ scand,
    const float4* __restrict__ srgb)
{
    int cx = (int)(px * (float)GR);   // x in [0,1): no clamp needed
    int cy = (int)(py * (float)GR);
    unsigned int e = sgrid[cy * GR + cx];

    float a = __fadd_rn(__fmul_rn(px, px), __fmul_rn(py, py));
    float bd = 3.4e38f;
    int bi = 0;

    // Uniform: always evaluate the two primary candidates.
    eval_cand(e & 0xFFu, px, py, a, scand, bd, bi);
    eval_cand((e >> 8) & 0xFFu, px, py, a, scand, bd, bi);

    unsigned int hi = e >> 16;
    if (hi != 0xFFFFu) {
        if (hi == 0xFEFEu) {
            // Degenerate cell: 5x5 coarse scan (ascending ids).
            bd = 3.4e38f; bi = 0;
            int ci = (int)(px * 10.0f);
            int cj = (int)(py * 10.0f);
            int i1 = min(9, ci + 2), j0 = max(0, cj - 2), j1 = min(9, cj + 2);
            for (int ii = max(0, ci - 2); ii <= i1; ii++)
                for (int jj = j0; jj <= j1; jj++)
                    eval_cand((unsigned int)(ii * 10 + jj), px, py, a, scand, bd, bi);
        } else {
            eval_cand(hi & 0xFFu, px, py, a, scand, bd, bi);
            eval_cand(hi >> 8, px, py, a, scand, bd, bi);
        }
    }
    return srgb[bi];
}

__global__ void __launch_bounds__(256, 6) voronoi_main(
    const float2* __restrict__ x, float* __restrict__ out, int n)
{
    __shared__ SmemTables st;

    {
        const uint4* gg = (const uint4*)g_grid;
        uint4* sg = (uint4*)st.grid;
        for (int i = threadIdx.x; i < NCELL / 4; i += 256) sg[i] = gg[i];
        if (threadIdx.x < NS) {
            st.cand[threadIdx.x] = g_cand[threadIdx.x];
            st.rgb[threadIdx.x]  = g_rgb[threadIdx.x];
        }
    }
    __syncthreads();

    int tid = blockIdx.x * blockDim.x + threadIdx.x;
    int stride = gridDim.x * blockDim.x;

    int i = tid;
    for (; i + stride < n; i += 2 * stride) {
        int j = i + stride;
        float2 p0 = x[i];
        float2 p1 = x[j];

        float4 c0 = lookup_one(p0.x, p0.y, st.grid, st.cand, st.rgb);
        float4 c1 = lookup_one(p1.x, p1.y, st.grid, st.cand, st.rgb);

        out[3 * i + 0] = c0.x;
        out[3 * i + 1] = c0.y;
        out[3 * i + 2] = c0.z;
        out[3 * j + 0] = c1.x;
        out[3 * j + 1] = c1.y;
        out[3 * j + 2] = c1.z;
    }
    if (i < n) {
        float2 p0 = x[i];
        float4 c0 = lookup_one(p0.x, p0.y, st.grid, st.cand, st.rgb);
        out[3 * i + 0] = c0.x;
        out[3 * i + 1] = c0.y;
        out[3 * i + 2] = c0.z;
    }
}

extern "C" void kernel_launch(void* const* d_in, const int* in_sizes, int n_in,
                              void* d_out, int out_size) {
    const float2* x = (const float2*)d_in[0];
    const float*  p = (const float*)d_in[1];
    float* out = (float*)d_out;
    int n = in_sizes[0] / 2;

    build_lut<<<(NCELL + 127) / 128, 128>>>(p);
    voronoi_main<<<888, 256>>>(x, out, n);
}

// round 9
// speedup vs baseline: 1.3482x; 1.2709x over previous
#include <cuda_runtime.h>

// Voronoi nearest-site via fine-grid candidate LUT, L1-resident tables.
// Reference-exact fp32 compare:
//   a  = rn(rn(x0^2) + rn(x1^2))
//   e  = fmaf(x1, sy, rn(x0*sx))
//   d2 = rn(rn(a - 2*e) + cs),  cs = rn(rn(sx^2) + rn(sy^2))
//   argmin: ascending candidate order, strict <  (lowest-index tie-break)
//
// R8 -> R9 (structural): NO shared memory. 64KB LUT + 3KB tables live in L1
// (228KB), one hot copy per SM shared by all warps; no per-CTA staging
// (saves 27MB L2 traffic). Zero smem + 32 regs -> 2048 threads/SM
// (16 warps/SMSP, +50% latency hiding vs smem builds). Streaming x/out use
// __ldcs/__stcs so they don't evict the LUT. GR=128 (power of 2: exact
// cell index, SHF addressing, thinner multi-candidate strip).

#define GR 128
#define NS 100
#define NCELL (GR * GR)

__device__ unsigned int g_grid[NCELL];
__device__ float4 g_cand[NS];   // sx, sy, cs, 0
__device__ float4 g_rgb[NS];    // r, g, b, 0

__global__ void build_lut(const float* __restrict__ p) {
    __shared__ float sp[2 * NS];
    for (int i = threadIdx.x; i < 2 * NS; i += blockDim.x) {
        int s = i >> 1;
        sp[i] = p[1 + 5 * s + (i & 1)];
    }
    __syncthreads();

    int cell = blockIdx.x * blockDim.x + threadIdx.x;
    if (cell >= NCELL) return;

    if (cell < NS) {
        float sx = sp[2 * cell], sy = sp[2 * cell + 1];
        float cs = __fadd_rn(__fmul_rn(sx, sx), __fmul_rn(sy, sy));
        g_cand[cell] = make_float4(sx, sy, cs, 0.0f);
        g_rgb[cell]  = make_float4(p[3 + 5 * cell], p[4 + 5 * cell], p[5 + 5 * cell], 0.0f);
    }

    int gy = cell >> 7;
    int gx = cell & (GR - 1);
    float cx = (gx + 0.5f) * (1.0f / GR);
    float cy = (gy + 0.5f) * (1.0f / GR);

    // 5x5 coarse window around the cell: contains the nearest site
    // (d <= 0.1415) and the whole candidate band (reach < 0.2).
    int ci = min(9, gx / 13), cj = min(9, gy / 13);   // coarse cell of center (approx ok: window below is clamped wide)
    ci = (int)(cx * 10.0f); cj = (int)(cy * 10.0f);
    int i0 = max(0, ci - 2), i1 = min(9, ci + 2);
    int j0 = max(0, cj - 2), j1 = min(9, cj + 2);

    // Pass 1: nearest d^2 from cell center over the window.
    float best = 3.4e38f;
    for (int ii = i0; ii <= i1; ii++)
        for (int jj = j0; jj <= j1; jj++) {
            int s = ii * 10 + jj;
            float dx = cx - sp[2 * s];
            float dy = cy - sp[2 * s + 1];
            best = fminf(best, fmaf(dx, dx, dy * dy));
        }

    // Band: d(c,s) < d(c,s*) + 2r + slack. 2r = sqrt(2)/128 = 0.011049;
    // slack 1e-4 covers boundary rounding + the reference formula's ~4e-7
    // d2 noise with huge margin.
    float thr = sqrtf(best) + 0.0110485f + 1e-4f;
    float thr2 = thr * thr;

    unsigned int entry = 0;
    int cnt = 0;
    for (int ii = i0; ii <= i1; ii++)
        for (int jj = j0; jj <= j1; jj++) {   // ascending site ids
            int s = ii * 10 + jj;
            float dx = cx - sp[2 * s];
            float dy = cy - sp[2 * s + 1];
            float d2 = fmaf(dx, dx, dy * dy);
            if (d2 <= thr2) {
                if (cnt < 4) entry |= ((unsigned int)s) << (8 * cnt);
                cnt++;
            }
        }
    if (cnt > 4) {
        entry = (entry & 0xFFu) | 0x0000FE00u | 0x00FF0000u | 0xFF000000u; // 5x5 fallback
    } else {
        for (int k = cnt; k < 4; k++) entry |= 0xFFu << (8 * k);
    }
    g_grid[cell] = entry;
}

__device__ __forceinline__ void eval_cand(
    unsigned int c, float px, float py, float a, float& bd, int& bi)
{
    float4 s = __ldg(&g_cand[c]);
    float ee = __fmaf_rn(py, s.y, __fmul_rn(px, s.x));
    float d2 = __fadd_rn(__fsub_rn(a, __fmul_rn(2.0f, ee)), s.z);
    if (d2 < bd) { bd = d2; bi = (int)c; }
}

__device__ __forceinline__ float4 lookup_one(float px, float py)
{
    // GR=128: multiply by 2^7 is exact; px in [0,1) -> cx in [0,127].
    int cx = (int)(px * (float)GR);
    int cy = (int)(py * (float)GR);
    unsigned int e = __ldg(&g_grid[(cy << 7) + cx]);

    int idx = (int)(e & 0xFFu);
    if ((e >> 8) != 0x00FFFFFFu) {
        float a = __fadd_rn(__fmul_rn(px, px), __fmul_rn(py, py));
        float bd = 3.4e38f;
        int bi = 0;
        if (((e >> 8) & 0xFFu) == 0xFEu) {
            // Rare: 5x5 coarse-neighborhood scan (ascending ids).
            int ci = (int)(px * 10.0f);
            int cj = (int)(py * 10.0f);
            int i1 = min(9, ci + 2), j0 = max(0, cj - 2), j1 = min(9, cj + 2);
            for (int ii = max(0, ci - 2); ii <= i1; ii++)
                for (int jj = j0; jj <= j1; jj++)
                    eval_cand((unsigned int)(ii * 10 + jj), px, py, a, bd, bi);
        } else {
            #pragma unroll
            for (int k = 0; k < 4; k++) {
                unsigned int c = (e >> (8 * k)) & 0xFFu;
                if (c == 0xFFu) break;
                eval_cand(c, px, py, a, bd, bi);
            }
        }
        idx = bi;
    }
    return __ldg(&g_rgb[idx]);
}

__global__ void __launch_bounds__(256, 8) voronoi_main(
    const float2* __restrict__ x, float* __restrict__ out, int n)
{
    int tid = blockIdx.x * blockDim.x + threadIdx.x;
    int stride = gridDim.x * blockDim.x;

    for (int i = tid; i < n; i += stride) {
        float2 pt = __ldcs(&x[i]);            // streaming: don't pollute L1
        float4 c = lookup_one(pt.x, pt.y);
        __stcs(&out[3 * i + 0], c.x);          // streaming stores
        __stcs(&out[3 * i + 1], c.y);
        __stcs(&out[3 * i + 2], c.z);
    }
}

extern "C" void kernel_launch(void* const* d_in, const int* in_sizes, int n_in,
                              void* d_out, int out_size) {
    const float2* x = (const float2*)d_in[0];
    const float*  p = (const float*)d_in[1];
    float* out = (float*)d_out;
    int n = in_sizes[0] / 2;

    build_lut<<<(NCELL + 127) / 128, 128>>>(p);
    voronoi_main<<<1184, 256>>>(x, out, n);   // 8 CTAs/SM x 148 = one full wave
}